// round 9
// baseline (speedup 1.0000x reference)
#include <cuda_runtime.h>
#include <math.h>
#include <stdint.h>

#define Bc 4
#define Tc 1024
#define Dc 1024
#define Hc 16
#define HSc 64
#define Lc 2047

__device__ float g_q[Bc * Tc * Dc];
__device__ float g_k[Bc * Tc * Dc];
__device__ float g_v[Bc * Tc * Dc];
__device__ float g_p[Lc * Dc];
__device__ float g_ctx[Bc * Tc * Dc];

__device__ __forceinline__ uint32_t tf32_of(float x) {
    uint32_t r;
    asm("cvt.rna.tf32.f32 %0, %1;" : "=r"(r) : "f"(x));
    return r;
}
__device__ __forceinline__ void mma_p(float* d, uint4 a, uint2 b) {
    asm volatile(
        "mma.sync.aligned.m16n8k8.row.col.f32.tf32.tf32.f32 "
        "{%0,%1,%2,%3},{%4,%5,%6,%7},{%8,%9},{%0,%1,%2,%3};"
        : "+f"(d[0]), "+f"(d[1]), "+f"(d[2]), "+f"(d[3])
        : "r"(a.x), "r"(a.y), "r"(a.z), "r"(a.w), "r"(b.x), "r"(b.y));
}

// ---- packed A fragments: per-oct block = RB*128+8 u32 ----
template <int RB>
__device__ __forceinline__ void storeA(uint32_t* sA, int oct, int r, const float* f) {
    uint32_t* b = sA + oct * (RB * 128 + 8) + (r >> 4) * 128 + (r & 7) * 16 + ((r >> 3) & 1);
    int gs = r & 3;
#pragma unroll
    for (int p = 0; p < 4; p++) {
        int tq = p ^ gs;
        b[p * 4] = tf32_of(f[tq]);
        b[p * 4 + 2] = tf32_of(f[tq + 4]);
    }
}
template <int RB>
__device__ __forceinline__ uint4 loadA(const uint32_t* sA, int oct, int rb, int gid, int tig) {
    return *(const uint4*)(sA + oct * (RB * 128 + 8) + rb * 128 + gid * 16 +
                           ((tig ^ (gid & 3)) << 2));
}
// ---- packed B fragments: per-oct block = 8*S+8 u32, S = stride in uint2 units ----
template <int S>
__device__ __forceinline__ void storeB(uint32_t* sB, int oct, int c, const float* f) {
    uint32_t* b = sB + oct * (S * 8 + 8) + c * 2;
#pragma unroll
    for (int tq = 0; tq < 4; tq++)
        *(uint2*)(b + tq * S * 2) = make_uint2(tf32_of(f[tq]), tf32_of(f[tq + 4]));
}
template <int S>
__device__ __forceinline__ uint2 loadB(const uint32_t* sB, int oct, int tig, int c) {
    return *(const uint2*)(sB + oct * (S * 8 + 8) + (tig * S + c) * 2);
}

__device__ __forceinline__ void ld8(const float* p, bool ok, float* f) {
    float4 z = make_float4(0.f, 0.f, 0.f, 0.f);
    float4 x0 = ok ? *(const float4*)p : z;
    float4 x1 = ok ? *(const float4*)(p + 4) : z;
    f[0] = x0.x; f[1] = x0.y; f[2] = x0.z; f[3] = x0.w;
    f[4] = x1.x; f[5] = x1.y; f[6] = x1.z; f[7] = x1.w;
}

// ============================================================
// GEMM body: C[M,N] = A @ W^T (+bias). 128x128, BK=16, packed tf32.
// ============================================================
__device__ __forceinline__ void gemm_body(const float* __restrict__ A,
                                          const float* __restrict__ W,
                                          const float* __restrict__ bias,
                                          float* __restrict__ C,
                                          int M, int N, int K, int m0, int n0) {
    __shared__ __align__(16) uint32_t sA[2][2 * (8 * 128 + 8)];
    __shared__ __align__(16) uint32_t sB[2][2 * (132 * 8 + 8)];
    const int tid = threadIdx.x;
    const int lrow = tid >> 1, oct = tid & 1, lk = oct * 8;
    const int lane = tid & 31, wid = tid >> 5;
    const int rb0 = (wid >> 1) * 2, nB = (wid & 1) * 64;
    const int gid = lane >> 2, tig = lane & 3;

    float acc[2][8][4];
#pragma unroll
    for (int i = 0; i < 2; i++)
#pragma unroll
        for (int j = 0; j < 8; j++)
#pragma unroll
            for (int c = 0; c < 4; c++) acc[i][j][c] = 0.f;

    const bool av = (m0 + lrow) < M, wv = (n0 + lrow) < N;
    const float* Ar = A + (size_t)(m0 + lrow) * K + lk;
    const float* Wr = W + (size_t)(n0 + lrow) * K + lk;
    float fA[8], fB[8];
    ld8(Ar, av, fA);
    ld8(Wr, wv, fB);
    storeA<8>(sA[0], oct, lrow, fA);
    storeB<132>(sB[0], oct, lrow, fB);
    __syncthreads();

    const int nk = K / 16;
    for (int kt = 0; kt < nk; kt++) {
        const int cur = kt & 1;
        const bool more = (kt + 1) < nk;
        if (more) {
            ld8(Ar + (kt + 1) * 16, av, fA);
            ld8(Wr + (kt + 1) * 16, wv, fB);
        }
#pragma unroll
        for (int o = 0; o < 2; o++) {
            uint4 a0 = loadA<8>(sA[cur], o, rb0, gid, tig);
            uint4 a1 = loadA<8>(sA[cur], o, rb0 + 1, gid, tig);
#pragma unroll
            for (int nt = 0; nt < 8; nt++) {
                uint2 bv = loadB<132>(sB[cur], o, tig, nB + nt * 8 + gid);
                mma_p(acc[0][nt], a0, bv);
                mma_p(acc[1][nt], a1, bv);
            }
        }
        if (more) {
            storeA<8>(sA[cur ^ 1], oct, lrow, fA);
            storeB<132>(sB[cur ^ 1], oct, lrow, fB);
            __syncthreads();
        }
    }

#pragma unroll
    for (int mt = 0; mt < 2; mt++) {
        int r = m0 + (rb0 + mt) * 16 + gid;
#pragma unroll
        for (int nt = 0; nt < 8; nt++) {
            int c = n0 + nB + nt * 8 + 2 * tig;
            float b0v = bias ? bias[c] : 0.f;
            float b1v = bias ? bias[c + 1] : 0.f;
            if (r < M)
                *(float2*)(C + (size_t)r * N + c) =
                    make_float2(acc[mt][nt][0] + b0v, acc[mt][nt][1] + b1v);
            if (r + 8 < M)
                *(float2*)(C + (size_t)(r + 8) * N + c) =
                    make_float2(acc[mt][nt][2] + b0v, acc[mt][nt][3] + b1v);
        }
    }
}

__global__ __launch_bounds__(256, 2) void gemm_tc_nt(
    const float* __restrict__ A, const float* __restrict__ W,
    const float* __restrict__ bias, float* __restrict__ C, int M, int N, int K) {
    gemm_body(A, W, bias, C, M, N, K, blockIdx.y * 128, blockIdx.x * 128);
}

// QKV + pos projections in one launch. grid (32, 32).
__global__ __launch_bounds__(256, 2) void gemm_qkvp(
    const float* __restrict__ A, const float* __restrict__ rpe,
    const float* __restrict__ Wq, const float* __restrict__ Wk, const float* __restrict__ Wv,
    const float* __restrict__ Wp,
    const float* __restrict__ bq, const float* __restrict__ bk, const float* __restrict__ bv,
    float* __restrict__ Cq, float* __restrict__ Ck, float* __restrict__ Cv,
    float* __restrict__ Cp) {
    const int sel = blockIdx.x >> 3;
    if (sel == 3) {
        if (blockIdx.y >= 16) return;
        gemm_body(rpe, Wp, nullptr, Cp, Lc, Dc, Dc, blockIdx.y * 128, (blockIdx.x & 7) * 128);
        return;
    }
    const float* W = (sel == 0) ? Wq : (sel == 1) ? Wk : Wv;
    const float* bias = (sel == 0) ? bq : (sel == 1) ? bk : bv;
    float* C = (sel == 0) ? Cq : (sel == 1) ? Ck : Cv;
    gemm_body(A, W, bias, C, Bc * Tc, Dc, Dc, blockIdx.y * 128, (blockIdx.x & 7) * 128);
}

// ============================================================
// FUSED attention per (bh, 16-row q tile) — 2 blocks/SM for MUFU overlap
// smem (u32): Sb 16*1028 | Au 8*136 | Av 8*136 | Bf 4608 | inv 16
// ============================================================
#define SB_STR 1028
#define AU_OFF (16 * SB_STR)
#define AV_OFF (AU_OFF + 8 * 136)
#define BF_OFF (AV_OFF + 8 * 136)
#define INV_OFF (BF_OFF + 4608)
#define FUSED_SMEM_BYTES ((INV_OFF + 16) * 4)

__global__ __launch_bounds__(256, 2) void fused_attn(
    const float* __restrict__ Q, const float* __restrict__ K,
    const float* __restrict__ P, const float* __restrict__ V,
    const float* __restrict__ u, const float* __restrict__ vb,
    float* __restrict__ probs, float* __restrict__ ctx) {
    extern __shared__ __align__(16) uint32_t su[];
    float* Sb = (float*)su;
    uint32_t* Au = su + AU_OFF;
    uint32_t* Av = su + AV_OFF;
    uint32_t* Bf0 = su + BF_OFF;
    float* inv_s = (float*)(su + INV_OFF);

    const int t = threadIdx.x;
    const int bh = blockIdx.y, zb = bh >> 4, h = bh & 15;
    const int q0 = blockIdx.x * 16;
    const int lane = t & 31, w = t >> 5;
    const int nBf = w * 8;               // warp covers 16 rows x 8 cols per strip
    const int gid = lane >> 2, tig = lane & 3;

    // ---- stage q+u (threads<128) / q+v (threads>=128) as packed A frags ----
    {
        int qr = (t >> 3) & 15, o = t & 7;
        const float* qp = Q + ((size_t)(zb * Tc) + q0 + qr) * Dc + h * HSc + o * 8;
        float a[8], bb[8];
        ld8(qp, true, a);
        if (t < 128) {
            ld8(u + h * HSc + o * 8, true, bb);
#pragma unroll
            for (int i = 0; i < 8; i++) bb[i] += a[i];
            storeA<1>(Au, o, qr, bb);
        } else {
            ld8(vb + h * HSc + o * 8, true, bb);
#pragma unroll
            for (int i = 0; i < 8; i++) bb[i] += a[i];
            storeA<1>(Av, o, qr, bb);
        }
    }

    const int kr = t >> 2, qq = t & 3;
    float f0[8], f1[8];

    // ================= phase 1: ac = (q+u) K^T (pipelined) =================
    {
        const float* kp = K + ((size_t)(zb * Tc) + kr) * Dc + h * HSc + qq * 16;
        ld8(kp, true, f0);
        ld8(kp + 8, true, f1);
    }
    for (int j0 = 0; j0 < Tc; j0 += 64) {
        __syncthreads();
        storeB<68>(Bf0, 2 * qq, kr, f0);
        storeB<68>(Bf0, 2 * qq + 1, kr, f1);
        __syncthreads();
        if (j0 + 64 < Tc) {
            const float* kp = K + ((size_t)(zb * Tc) + j0 + 64 + kr) * Dc + h * HSc + qq * 16;
            ld8(kp, true, f0);
            ld8(kp + 8, true, f1);
        }

        float acc[4] = {0.f, 0.f, 0.f, 0.f};
#pragma unroll
        for (int o = 0; o < 8; o++) {
            uint4 a = loadA<1>(Au, o, 0, gid, tig);
            mma_p(acc, a, loadB<68>(Bf0, o, tig, nBf + gid));
        }
        int col = j0 + nBf + 2 * tig;
        *(float2*)&Sb[gid * SB_STR + col] = make_float2(acc[0], acc[1]);
        *(float2*)&Sb[(gid + 8) * SB_STR + col] = make_float2(acc[2], acc[3]);
    }

    // ================= phase 2: bd band, scatter-add (pipelined) =================
    const int lStart = (Tc - 1) - (q0 + 15);
    {
        int l = lStart + kr;
        if (l < Lc) {
            const float* pp = P + (size_t)l * Dc + h * HSc + qq * 16;
            ld8(pp, true, f0);
            ld8(pp + 8, true, f1);
        } else {
#pragma unroll
            for (int i = 0; i < 8; i++) { f0[i] = 0.f; f1[i] = 0.f; }
        }
    }
    for (int it = 0; it < 17; it++) {
        int lBase = lStart + it * 64;
        __syncthreads();
        storeB<68>(Bf0, 2 * qq, kr, f0);
        storeB<68>(Bf0, 2 * qq + 1, kr, f1);
        __syncthreads();
        if (it + 1 < 17) {
            int l = lBase + 64 + kr;
            if (l < Lc) {
                const float* pp = P + (size_t)l * Dc + h * HSc + qq * 16;
                ld8(pp, true, f0);
                ld8(pp + 8, true, f1);
            } else {
#pragma unroll
                for (int i = 0; i < 8; i++) { f0[i] = 0.f; f1[i] = 0.f; }
            }
        }

        float acc[4] = {0.f, 0.f, 0.f, 0.f};
#pragma unroll
        for (int o = 0; o < 8; o++) {
            uint4 a = loadA<1>(Av, o, 0, gid, tig);
            mma_p(acc, a, loadB<68>(Bf0, o, tig, nBf + gid));
        }
        int lc = lBase + nBf + 2 * tig;
        int j = (q0 + gid) + lc - (Tc - 1);
        if (j >= 0 && j < Tc) Sb[gid * SB_STR + j] += acc[0];
        if (j + 1 >= 0 && j + 1 < Tc) Sb[gid * SB_STR + j + 1] += acc[1];
        int j2 = j + 8;
        if (j2 >= 0 && j2 < Tc) Sb[(gid + 8) * SB_STR + j2] += acc[2];
        if (j2 + 1 >= 0 && j2 + 1 < Tc) Sb[(gid + 8) * SB_STR + j2 + 1] += acc[3];
    }
    __syncthreads();

    // ===== phase 3: softmax numerators (store raw e; inv kept aside) =====
#pragma unroll
    for (int rr = 0; rr < 2; rr++) {
        int row_i = w * 2 + rr;
        float* row = Sb + row_i * SB_STR;
        float mx = -3.4e38f;
        for (int c = lane; c < Tc; c += 32) mx = fmaxf(mx, row[c]);
#pragma unroll
        for (int o = 16; o; o >>= 1) mx = fmaxf(mx, __shfl_xor_sync(0xffffffffu, mx, o));
        float sum = 0.f;
        for (int c = lane; c < Tc; c += 32) {
            float e = __expf(0.125f * (row[c] - mx));
            row[c] = e;
            sum += e;
        }
#pragma unroll
        for (int o = 16; o; o >>= 1) sum += __shfl_xor_sync(0xffffffffu, sum, o);
        if (lane == 0) inv_s[row_i] = 1.f / sum;
    }
    __syncthreads();

    // ---- write probs = e * inv (single pass) ----
    {
        float* pb = probs + ((size_t)bh << 20) + (size_t)q0 * Tc;
#pragma unroll 4
        for (int r = 0; r < 16; r++) {
            float iv = inv_s[r];
            float4 val = *(float4*)&Sb[r * SB_STR + 4 * t];
            val.x *= iv; val.y *= iv; val.z *= iv; val.w *= iv;
            *(float4*)(pb + (size_t)r * Tc + 4 * t) = val;
        }
    }

    // ================= phase 4: ctx = (e @ V) * inv (pipelined) =================
    uint32_t* Vt = Bf0;  // 64*72 u32
    float acc2[4] = {0.f, 0.f, 0.f, 0.f};
    float fv[16];
    {
        const float* vp = V + ((size_t)(zb * Tc) + kr) * Dc + h * HSc + qq * 16;
        ld8(vp, true, fv);
        ld8(vp + 8, true, fv + 8);
    }
    for (int kc = 0; kc < Tc; kc += 64) {
        __syncthreads();
        uint32_t* dst = Vt + kr * 72 + qq * 16;
        *(uint4*)(dst + 0)  = make_uint4(tf32_of(fv[0]),  tf32_of(fv[1]),  tf32_of(fv[2]),  tf32_of(fv[3]));
        *(uint4*)(dst + 4)  = make_uint4(tf32_of(fv[4]),  tf32_of(fv[5]),  tf32_of(fv[6]),  tf32_of(fv[7]));
        *(uint4*)(dst + 8)  = make_uint4(tf32_of(fv[8]),  tf32_of(fv[9]),  tf32_of(fv[10]), tf32_of(fv[11]));
        *(uint4*)(dst + 12) = make_uint4(tf32_of(fv[12]), tf32_of(fv[13]), tf32_of(fv[14]), tf32_of(fv[15]));
        __syncthreads();
        if (kc + 64 < Tc) {
            const float* vp = V + ((size_t)(zb * Tc) + kc + 64 + kr) * Dc + h * HSc + qq * 16;
            ld8(vp, true, fv);
            ld8(vp + 8, true, fv + 8);
        }

        const float* ar0 = Sb + gid * SB_STR + kc;
        const float* ar8 = ar0 + 8 * SB_STR;
#pragma unroll
        for (int o = 0; o < 8; o++) {
            uint4 a;
            a.x = tf32_of(ar0[o * 8 + tig]);
            a.y = tf32_of(ar8[o * 8 + tig]);
            a.z = tf32_of(ar0[o * 8 + tig + 4]);
            a.w = tf32_of(ar8[o * 8 + tig + 4]);
            uint2 b;
            b.x = Vt[(o * 8 + tig) * 72 + nBf + gid];
            b.y = Vt[(o * 8 + tig + 4) * 72 + nBf + gid];
            mma_p(acc2, a, b);
        }
    }
    {
        int r = q0 + gid;
        float iv0 = inv_s[gid], iv8 = inv_s[gid + 8];
        int c = nBf + 2 * tig;
        *(float2*)(ctx + ((size_t)(zb * Tc) + r) * Dc + h * HSc + c) =
            make_float2(acc2[0] * iv0, acc2[1] * iv0);
        *(float2*)(ctx + ((size_t)(zb * Tc) + r + 8) * Dc + h * HSc + c) =
            make_float2(acc2[2] * iv8, acc2[3] * iv8);
    }
}

// ============================================================
extern "C" void kernel_launch(void* const* d_in, const int* in_sizes, int n_in,
                              void* d_out, int out_size) {
    const float* hs  = (const float*)d_in[0];
    const float* rpe = (const float*)d_in[1];
    const float* Wq  = (const float*)d_in[2];
    const float* bq  = (const float*)d_in[3];
    const float* Wk  = (const float*)d_in[4];
    const float* bk  = (const float*)d_in[5];
    const float* Wv  = (const float*)d_in[6];
    const float* bv  = (const float*)d_in[7];
    const float* Wo  = (const float*)d_in[8];
    const float* bo  = (const float*)d_in[9];
    const float* Wp  = (const float*)d_in[10];
    const float* pu  = (const float*)d_in[11];
    const float* pvb = (const float*)d_in[12];

    float* out = (float*)d_out;
    float* S   = out + (size_t)Bc * Tc * Dc;

    float *pq, *pk, *pv, *pp, *pctx;
    cudaGetSymbolAddress((void**)&pq,   g_q);
    cudaGetSymbolAddress((void**)&pk,   g_k);
    cudaGetSymbolAddress((void**)&pv,   g_v);
    cudaGetSymbolAddress((void**)&pp,   g_p);
    cudaGetSymbolAddress((void**)&pctx, g_ctx);

    cudaFuncSetAttribute(fused_attn, cudaFuncAttributeMaxDynamicSharedMemorySize,
                         FUSED_SMEM_BYTES);

    dim3 thr(256);
    gemm_qkvp<<<dim3(32, 32), thr>>>(hs, rpe, Wq, Wk, Wv, Wp, bq, bk, bv,
                                     pq, pk, pv, pp);

    fused_attn<<<dim3(Tc / 16, Bc * Hc), thr, FUSED_SMEM_BYTES>>>(
        pq, pk, pp, pv, pu, pvb, S, pctx);

    gemm_tc_nt<<<dim3(8, 32), thr>>>(pctx, Wo, bo, out, Bc * Tc, Dc, Dc);
}

// round 10
// speedup vs baseline: 1.2797x; 1.2797x over previous
#include <cuda_runtime.h>
#include <math.h>
#include <stdint.h>

#define Bc 4
#define Tc 1024
#define Dc 1024
#define Hc 16
#define HSc 64
#define Lc 2047

__device__ float g_q[Bc * Tc * Dc];
__device__ float g_k[Bc * Tc * Dc];
__device__ float g_v[Bc * Tc * Dc];
__device__ float g_p[Lc * Dc];
__device__ float g_ctx[Bc * Tc * Dc];

__device__ __forceinline__ uint32_t tf32_of(float x) {
    uint32_t r;
    asm("cvt.rna.tf32.f32 %0, %1;" : "=r"(r) : "f"(x));
    return r;
}
__device__ __forceinline__ void mma_p(float* d, uint4 a, uint2 b) {
    asm volatile(
        "mma.sync.aligned.m16n8k8.row.col.f32.tf32.tf32.f32 "
        "{%0,%1,%2,%3},{%4,%5,%6,%7},{%8,%9},{%0,%1,%2,%3};"
        : "+f"(d[0]), "+f"(d[1]), "+f"(d[2]), "+f"(d[3])
        : "r"(a.x), "r"(a.y), "r"(a.z), "r"(a.w), "r"(b.x), "r"(b.y));
}

// ---- packed A fragments: per-oct block = RB*128+8 u32 ----
template <int RB>
__device__ __forceinline__ void storeA(uint32_t* sA, int oct, int r, const float* f) {
    uint32_t* b = sA + oct * (RB * 128 + 8) + (r >> 4) * 128 + (r & 7) * 16 + ((r >> 3) & 1);
    int gs = r & 3;
#pragma unroll
    for (int p = 0; p < 4; p++) {
        int tq = p ^ gs;
        b[p * 4] = tf32_of(f[tq]);
        b[p * 4 + 2] = tf32_of(f[tq + 4]);
    }
}
template <int RB>
__device__ __forceinline__ uint4 loadA(const uint32_t* sA, int oct, int rb, int gid, int tig) {
    return *(const uint4*)(sA + oct * (RB * 128 + 8) + rb * 128 + gid * 16 +
                           ((tig ^ (gid & 3)) << 2));
}
// ---- packed B fragments: per-oct block = 8*S+8 u32, S = stride in uint2 units ----
template <int S>
__device__ __forceinline__ void storeB(uint32_t* sB, int oct, int c, const float* f) {
    uint32_t* b = sB + oct * (S * 8 + 8) + c * 2;
#pragma unroll
    for (int tq = 0; tq < 4; tq++)
        *(uint2*)(b + tq * S * 2) = make_uint2(tf32_of(f[tq]), tf32_of(f[tq + 4]));
}
template <int S>
__device__ __forceinline__ uint2 loadB(const uint32_t* sB, int oct, int tig, int c) {
    return *(const uint2*)(sB + oct * (S * 8 + 8) + (tig * S + c) * 2);
}

__device__ __forceinline__ void ld8(const float* p, bool ok, float* f) {
    float4 z = make_float4(0.f, 0.f, 0.f, 0.f);
    float4 x0 = ok ? *(const float4*)p : z;
    float4 x1 = ok ? *(const float4*)(p + 4) : z;
    f[0] = x0.x; f[1] = x0.y; f[2] = x0.z; f[3] = x0.w;
    f[4] = x1.x; f[5] = x1.y; f[6] = x1.z; f[7] = x1.w;
}

// ============================================================
// GEMM body: C[M,N] = A @ W^T (+bias). 128x128, BK=16, packed tf32.
// ============================================================
__device__ __forceinline__ void gemm_body(const float* __restrict__ A,
                                          const float* __restrict__ W,
                                          const float* __restrict__ bias,
                                          float* __restrict__ C,
                                          int M, int N, int K, int m0, int n0) {
    __shared__ __align__(16) uint32_t sA[2][2 * (8 * 128 + 8)];
    __shared__ __align__(16) uint32_t sB[2][2 * (132 * 8 + 8)];
    const int tid = threadIdx.x;
    const int lrow = tid >> 1, oct = tid & 1, lk = oct * 8;
    const int lane = tid & 31, wid = tid >> 5;
    const int rb0 = (wid >> 1) * 2, nB = (wid & 1) * 64;
    const int gid = lane >> 2, tig = lane & 3;

    float acc[2][8][4];
#pragma unroll
    for (int i = 0; i < 2; i++)
#pragma unroll
        for (int j = 0; j < 8; j++)
#pragma unroll
            for (int c = 0; c < 4; c++) acc[i][j][c] = 0.f;

    const bool av = (m0 + lrow) < M, wv = (n0 + lrow) < N;
    const float* Ar = A + (size_t)(m0 + lrow) * K + lk;
    const float* Wr = W + (size_t)(n0 + lrow) * K + lk;
    float fA[8], fB[8];
    ld8(Ar, av, fA);
    ld8(Wr, wv, fB);
    storeA<8>(sA[0], oct, lrow, fA);
    storeB<132>(sB[0], oct, lrow, fB);
    __syncthreads();

    const int nk = K / 16;
    for (int kt = 0; kt < nk; kt++) {
        const int cur = kt & 1;
        const bool more = (kt + 1) < nk;
        if (more) {
            ld8(Ar + (kt + 1) * 16, av, fA);
            ld8(Wr + (kt + 1) * 16, wv, fB);
        }
#pragma unroll
        for (int o = 0; o < 2; o++) {
            uint4 a0 = loadA<8>(sA[cur], o, rb0, gid, tig);
            uint4 a1 = loadA<8>(sA[cur], o, rb0 + 1, gid, tig);
#pragma unroll
            for (int nt = 0; nt < 8; nt++) {
                uint2 bv = loadB<132>(sB[cur], o, tig, nB + nt * 8 + gid);
                mma_p(acc[0][nt], a0, bv);
                mma_p(acc[1][nt], a1, bv);
            }
        }
        if (more) {
            storeA<8>(sA[cur ^ 1], oct, lrow, fA);
            storeB<132>(sB[cur ^ 1], oct, lrow, fB);
            __syncthreads();
        }
    }

#pragma unroll
    for (int mt = 0; mt < 2; mt++) {
        int r = m0 + (rb0 + mt) * 16 + gid;
#pragma unroll
        for (int nt = 0; nt < 8; nt++) {
            int c = n0 + nB + nt * 8 + 2 * tig;
            float b0v = bias ? bias[c] : 0.f;
            float b1v = bias ? bias[c + 1] : 0.f;
            if (r < M)
                *(float2*)(C + (size_t)r * N + c) =
                    make_float2(acc[mt][nt][0] + b0v, acc[mt][nt][1] + b1v);
            if (r + 8 < M)
                *(float2*)(C + (size_t)(r + 8) * N + c) =
                    make_float2(acc[mt][nt][2] + b0v, acc[mt][nt][3] + b1v);
        }
    }
}

__global__ __launch_bounds__(256, 2) void gemm_tc_nt(
    const float* __restrict__ A, const float* __restrict__ W,
    const float* __restrict__ bias, float* __restrict__ C, int M, int N, int K) {
    gemm_body(A, W, bias, C, M, N, K, blockIdx.y * 128, blockIdx.x * 128);
}

// QKV + pos projections in one launch. grid (32, 32).
__global__ __launch_bounds__(256, 2) void gemm_qkvp(
    const float* __restrict__ A, const float* __restrict__ rpe,
    const float* __restrict__ Wq, const float* __restrict__ Wk, const float* __restrict__ Wv,
    const float* __restrict__ Wp,
    const float* __restrict__ bq, const float* __restrict__ bk, const float* __restrict__ bv,
    float* __restrict__ Cq, float* __restrict__ Ck, float* __restrict__ Cv,
    float* __restrict__ Cp) {
    const int sel = blockIdx.x >> 3;
    if (sel == 3) {
        if (blockIdx.y >= 16) return;
        gemm_body(rpe, Wp, nullptr, Cp, Lc, Dc, Dc, blockIdx.y * 128, (blockIdx.x & 7) * 128);
        return;
    }
    const float* W = (sel == 0) ? Wq : (sel == 1) ? Wk : Wv;
    const float* bias = (sel == 0) ? bq : (sel == 1) ? bk : bv;
    float* C = (sel == 0) ? Cq : (sel == 1) ? Ck : Cv;
    gemm_body(A, W, bias, C, Bc * Tc, Dc, Dc, blockIdx.y * 128, (blockIdx.x & 7) * 128);
}

// ============================================================
// FUSED attention per (bh, 32-row q tile) — pipelined strips;
// exp folded into phase-4 pipeline (MUFU overlaps tensor/LDS).
// smem (u32): Sb 32*1028 | Au 8*264 | Av 8*264 | Bf 2*4416 | mx 32 | inv 32
// ============================================================
#define SB_STR 1028
#define AU_OFF (32 * SB_STR)
#define AV_OFF (AU_OFF + 8 * 264)
#define BF_OFF (AV_OFF + 8 * 264)
#define MX_OFF (BF_OFF + 2 * 4416)
#define INV_OFF (MX_OFF + 32)
#define FUSED_SMEM_BYTES ((INV_OFF + 32) * 4)

__global__ __launch_bounds__(256, 1) void fused_attn(
    const float* __restrict__ Q, const float* __restrict__ K,
    const float* __restrict__ P, const float* __restrict__ V,
    const float* __restrict__ u, const float* __restrict__ vb,
    float* __restrict__ probs, float* __restrict__ ctx) {
    extern __shared__ __align__(16) uint32_t su[];
    float* Sb = (float*)su;
    uint32_t* Au = su + AU_OFF;
    uint32_t* Av = su + AV_OFF;
    uint32_t* Bf0 = su + BF_OFF;
    float* mx_s = (float*)(su + MX_OFF);
    float* inv_s = (float*)(su + INV_OFF);

    const int t = threadIdx.x;
    const int bh = blockIdx.y, zb = bh >> 4, h = bh & 15;
    const int q0 = blockIdx.x * 32;
    const int lane = t & 31, w = t >> 5;
    const int mB = (w & 1) * 16, rbw = w & 1, nBf = (w >> 1) * 16;
    const int gid = lane >> 2, tig = lane & 3;

    // ---- stage q+u / q+v as packed A fragments (once) ----
    {
        int qr = t >> 3, o = t & 7;
        const float* qp = Q + ((size_t)(zb * Tc) + q0 + qr) * Dc + h * HSc + o * 8;
        const float* up = u + h * HSc + o * 8;
        const float* vp = vb + h * HSc + o * 8;
        float a[8], uu[8], fv[8];
        ld8(qp, true, a);
        ld8(up, true, uu);
        ld8(vp, true, fv);
        float fu2[8], fv2[8];
#pragma unroll
        for (int i = 0; i < 8; i++) { fu2[i] = a[i] + uu[i]; fv2[i] = a[i] + fv[i]; }
        storeA<2>(Au, o, qr, fu2);
        storeA<2>(Av, o, qr, fv2);
    }

    const int kr = t >> 2, qq = t & 3;
    float f0[8], f1[8];

    // ================= phase 1: ac = (q+u) K^T (pipelined) =================
    {
        const float* kp = K + ((size_t)(zb * Tc) + kr) * Dc + h * HSc + qq * 16;
        ld8(kp, true, f0);
        ld8(kp + 8, true, f1);
    }
    for (int j0 = 0; j0 < Tc; j0 += 64) {
        __syncthreads();
        storeB<68>(Bf0, 2 * qq, kr, f0);
        storeB<68>(Bf0, 2 * qq + 1, kr, f1);
        __syncthreads();
        if (j0 + 64 < Tc) {
            const float* kp = K + ((size_t)(zb * Tc) + j0 + 64 + kr) * Dc + h * HSc + qq * 16;
            ld8(kp, true, f0);
            ld8(kp + 8, true, f1);
        }

        float acc[2][4] = {{0.f, 0.f, 0.f, 0.f}, {0.f, 0.f, 0.f, 0.f}};
#pragma unroll
        for (int o = 0; o < 8; o++) {
            uint4 a = loadA<2>(Au, o, rbw, gid, tig);
#pragma unroll
            for (int nt = 0; nt < 2; nt++)
                mma_p(acc[nt], a, loadB<68>(Bf0, o, tig, nBf + nt * 8 + gid));
        }
#pragma unroll
        for (int nt = 0; nt < 2; nt++) {
            int col = j0 + nBf + nt * 8 + 2 * tig;
            *(float2*)&Sb[(mB + gid) * SB_STR + col] = make_float2(acc[nt][0], acc[nt][1]);
            *(float2*)&Sb[(mB + gid + 8) * SB_STR + col] = make_float2(acc[nt][2], acc[nt][3]);
        }
    }

    // ================= phase 2: bd band, scatter-add (pipelined) =================
    const int lStart = (Tc - 1) - (q0 + 31);
    {
        int l = lStart + kr;
        if (l < Lc) {
            const float* pp = P + (size_t)l * Dc + h * HSc + qq * 16;
            ld8(pp, true, f0);
            ld8(pp + 8, true, f1);
        } else {
#pragma unroll
            for (int i = 0; i < 8; i++) { f0[i] = 0.f; f1[i] = 0.f; }
        }
    }
    for (int it = 0; it < 17; it++) {
        int lBase = lStart + it * 64;
        __syncthreads();
        storeB<68>(Bf0, 2 * qq, kr, f0);
        storeB<68>(Bf0, 2 * qq + 1, kr, f1);
        __syncthreads();
        if (it + 1 < 17) {
            int l = lBase + 64 + kr;
            if (l < Lc) {
                const float* pp = P + (size_t)l * Dc + h * HSc + qq * 16;
                ld8(pp, true, f0);
                ld8(pp + 8, true, f1);
            } else {
#pragma unroll
                for (int i = 0; i < 8; i++) { f0[i] = 0.f; f1[i] = 0.f; }
            }
        }

        float acc[2][4] = {{0.f, 0.f, 0.f, 0.f}, {0.f, 0.f, 0.f, 0.f}};
#pragma unroll
        for (int o = 0; o < 8; o++) {
            uint4 a = loadA<2>(Av, o, rbw, gid, tig);
#pragma unroll
            for (int nt = 0; nt < 2; nt++)
                mma_p(acc[nt], a, loadB<68>(Bf0, o, tig, nBf + nt * 8 + gid));
        }
#pragma unroll
        for (int nt = 0; nt < 2; nt++) {
            int lc = lBase + nBf + nt * 8 + 2 * tig;
            int m = mB + gid;
            int j = (q0 + m) + lc - (Tc - 1);
            if (j >= 0 && j < Tc) Sb[m * SB_STR + j] += acc[nt][0];
            if (j + 1 >= 0 && j + 1 < Tc) Sb[m * SB_STR + j + 1] += acc[nt][1];
            int j2 = j + 8;
            if (j2 >= 0 && j2 < Tc) Sb[(m + 8) * SB_STR + j2] += acc[nt][2];
            if (j2 + 1 >= 0 && j2 + 1 < Tc) Sb[(m + 8) * SB_STR + j2 + 1] += acc[nt][3];
        }
    }
    __syncthreads();

    // ===== phase 3a: row max only (no MUFU) =====
#pragma unroll
    for (int rr = 0; rr < 4; rr++) {
        int row_i = w * 4 + rr;
        const float* row = Sb + row_i * SB_STR;
        float mx = -3.4e38f;
        for (int c = lane; c < Tc; c += 32) mx = fmaxf(mx, row[c]);
#pragma unroll
        for (int o = 16; o; o >>= 1) mx = fmaxf(mx, __shfl_xor_sync(0xffffffffu, mx, o));
        if (lane == 0) mx_s[row_i] = mx;
    }
    __syncthreads();

    // ===== phase 4: exp (MUFU) folded into ctx pipeline =====
    const int row_e = t >> 3;               // exp role: one row slice per thread
    const int ce = (t & 7) * 8;
    const float mxe = mx_s[row_e];
    float psum = 0.f;
    float* erow = Sb + row_e * SB_STR;

    // exp strip 0
    {
        float4 x0 = *(float4*)&erow[ce];
        float4 x1 = *(float4*)&erow[ce + 4];
        x0.x = __expf(0.125f * (x0.x - mxe)); x0.y = __expf(0.125f * (x0.y - mxe));
        x0.z = __expf(0.125f * (x0.z - mxe)); x0.w = __expf(0.125f * (x0.w - mxe));
        x1.x = __expf(0.125f * (x1.x - mxe)); x1.y = __expf(0.125f * (x1.y - mxe));
        x1.z = __expf(0.125f * (x1.z - mxe)); x1.w = __expf(0.125f * (x1.w - mxe));
        *(float4*)&erow[ce] = x0;
        *(float4*)&erow[ce + 4] = x1;
        psum += x0.x + x0.y + x0.z + x0.w + x1.x + x1.y + x1.z + x1.w;
    }

    uint32_t* Vt = Bf0;  // 64*72 u32
    float acc2[2][4] = {{0.f, 0.f, 0.f, 0.f}, {0.f, 0.f, 0.f, 0.f}};
    float fv[16];
    {
        const float* vp = V + ((size_t)(zb * Tc) + kr) * Dc + h * HSc + qq * 16;
        ld8(vp, true, fv);
        ld8(vp + 8, true, fv + 8);
    }
    for (int kc = 0; kc < Tc; kc += 64) {
        __syncthreads();   // prev MMA done with Vt; exp(kc) complete block-wide
        uint32_t* dst = Vt + kr * 72 + qq * 16;
        *(uint4*)(dst + 0)  = make_uint4(tf32_of(fv[0]),  tf32_of(fv[1]),  tf32_of(fv[2]),  tf32_of(fv[3]));
        *(uint4*)(dst + 4)  = make_uint4(tf32_of(fv[4]),  tf32_of(fv[5]),  tf32_of(fv[6]),  tf32_of(fv[7]));
        *(uint4*)(dst + 8)  = make_uint4(tf32_of(fv[8]),  tf32_of(fv[9]),  tf32_of(fv[10]), tf32_of(fv[11]));
        *(uint4*)(dst + 12) = make_uint4(tf32_of(fv[12]), tf32_of(fv[13]), tf32_of(fv[14]), tf32_of(fv[15]));
        __syncthreads();
        if (kc + 64 < Tc) {
            // prefetch V strip kc+64 (gmem) and exp strip kc+64 (MUFU) —
            // both retire under this strip's MMA/LDS work across warps.
            const float* vp = V + ((size_t)(zb * Tc) + kc + 64 + kr) * Dc + h * HSc + qq * 16;
            ld8(vp, true, fv);
            ld8(vp + 8, true, fv + 8);
            float* ep = erow + kc + 64 + ce;
            float4 x0 = *(float4*)ep;
            float4 x1 = *(float4*)(ep + 4);
            x0.x = __expf(0.125f * (x0.x - mxe)); x0.y = __expf(0.125f * (x0.y - mxe));
            x0.z = __expf(0.125f * (x0.z - mxe)); x0.w = __expf(0.125f * (x0.w - mxe));
            x1.x = __expf(0.125f * (x1.x - mxe)); x1.y = __expf(0.125f * (x1.y - mxe));
            x1.z = __expf(0.125f * (x1.z - mxe)); x1.w = __expf(0.125f * (x1.w - mxe));
            *(float4*)ep = x0;
            *(float4*)(ep + 4) = x1;
            psum += x0.x + x0.y + x0.z + x0.w + x1.x + x1.y + x1.z + x1.w;
        }

        const float* ar0 = Sb + (mB + gid) * SB_STR + kc;
        const float* ar8 = ar0 + 8 * SB_STR;
#pragma unroll
        for (int o = 0; o < 8; o++) {
            uint4 a;
            a.x = tf32_of(ar0[o * 8 + tig]);
            a.y = tf32_of(ar8[o * 8 + tig]);
            a.z = tf32_of(ar0[o * 8 + tig + 4]);
            a.w = tf32_of(ar8[o * 8 + tig + 4]);
#pragma unroll
            for (int nt = 0; nt < 2; nt++) {
                int c = nBf + nt * 8 + gid;
                uint2 b;
                b.x = Vt[(o * 8 + tig) * 72 + c];
                b.y = Vt[(o * 8 + tig + 4) * 72 + c];
                mma_p(acc2[nt], a, b);
            }
        }
    }

    // ---- row-sum reduce over the 8 lanes sharing a row ----
#pragma unroll
    for (int o = 4; o; o >>= 1) psum += __shfl_xor_sync(0xffffffffu, psum, o);
    if ((lane & 7) == 0) inv_s[row_e] = 1.f / psum;
    __syncthreads();

    // ---- write probs = e * inv (single pass) ----
    {
        float* pb = probs + ((size_t)bh << 20) + (size_t)q0 * Tc;
#pragma unroll 4
        for (int r = 0; r < 32; r++) {
            float iv = inv_s[r];
            float4 val = *(float4*)&Sb[r * SB_STR + 4 * t];
            val.x *= iv; val.y *= iv; val.z *= iv; val.w *= iv;
            *(float4*)(pb + (size_t)r * Tc + 4 * t) = val;
        }
    }

    // ---- ctx epilogue: scale by inv ----
    {
        int r = q0 + mB + gid;
        float iv0 = inv_s[mB + gid], iv8 = inv_s[mB + gid + 8];
#pragma unroll
        for (int nt = 0; nt < 2; nt++) {
            int c = nBf + nt * 8 + 2 * tig;
            *(float2*)(ctx + ((size_t)(zb * Tc) + r) * Dc + h * HSc + c) =
                make_float2(acc2[nt][0] * iv0, acc2[nt][1] * iv0);
            *(float2*)(ctx + ((size_t)(zb * Tc) + r + 8) * Dc + h * HSc + c) =
                make_float2(acc2[nt][2] * iv8, acc2[nt][3] * iv8);
        }
    }
}

// ============================================================
extern "C" void kernel_launch(void* const* d_in, const int* in_sizes, int n_in,
                              void* d_out, int out_size) {
    const float* hs  = (const float*)d_in[0];
    const float* rpe = (const float*)d_in[1];
    const float* Wq  = (const float*)d_in[2];
    const float* bq  = (const float*)d_in[3];
    const float* Wk  = (const float*)d_in[4];
    const float* bk  = (const float*)d_in[5];
    const float* Wv  = (const float*)d_in[6];
    const float* bv  = (const float*)d_in[7];
    const float* Wo  = (const float*)d_in[8];
    const float* bo  = (const float*)d_in[9];
    const float* Wp  = (const float*)d_in[10];
    const float* pu  = (const float*)d_in[11];
    const float* pvb = (const float*)d_in[12];

    float* out = (float*)d_out;
    float* S   = out + (size_t)Bc * Tc * Dc;

    float *pq, *pk, *pv, *pp, *pctx;
    cudaGetSymbolAddress((void**)&pq,   g_q);
    cudaGetSymbolAddress((void**)&pk,   g_k);
    cudaGetSymbolAddress((void**)&pv,   g_v);
    cudaGetSymbolAddress((void**)&pp,   g_p);
    cudaGetSymbolAddress((void**)&pctx, g_ctx);

    cudaFuncSetAttribute(fused_attn, cudaFuncAttributeMaxDynamicSharedMemorySize,
                         FUSED_SMEM_BYTES);

    dim3 thr(256);
    gemm_qkvp<<<dim3(32, 32), thr>>>(hs, rpe, Wq, Wk, Wv, Wp, bq, bk, bv,
                                     pq, pk, pv, pp);

    fused_attn<<<dim3(Tc / 32, Bc * Hc), thr, FUSED_SMEM_BYTES>>>(
        pq, pk, pp, pv, pu, pvb, S, pctx);

    gemm_tc_nt<<<dim3(8, 32), thr>>>(pctx, Wo, bo, out, Bc * Tc, Dc, Dc);
}